// round 10
// baseline (speedup 1.0000x reference)
#include <cuda_runtime.h>

#define BB 2
#define LL 512
#define DD 256
#define NN 256
#define DT 64
#define PW 576   // DT + 2*DD

// scratch (device globals — no allocations allowed); padded for the scan's
// over-prefetch past the end (values loaded but never used).
__device__ float  g_proj[(BB * LL + 16) * PW];     // only cols [0,64) (dt_raw) used now
__device__ float2 g_ddxT[BB * DD * LL + 64];       // {dt, dt*x} at [(b*DD+d)*LL + l]
__device__ float2 g_bg2 [(BB * LL + 16) * NN];     // {beta_n, gamma_n} per (row, n)

__device__ __forceinline__ float ex2_approx(float x) {
    float r;
    asm("ex2.approx.ftz.f32 %0, %1;" : "=f"(r) : "f"(x));
    return r;
}

// ---------------------------------------------------------------------------
// Kernel 1: proj = x @ W_in   ([1024,256] x [256,576] -> [1024,576])
// 32x64 tiles (grid 9 x 32 = 288 CTAs ~= 2/SM), kc=32, double-buffered smem,
// 128 threads, 4x4 micro-tile. Epilogue routes by tile column class:
//   bn=0 -> dt_raw into g_proj; bn in [64,320) -> beta into g_bg2[.].x;
//   bn in [320,576) -> gamma into g_bg2[.].y  (packed layout, no repack pass).
// ---------------------------------------------------------------------------
__global__ void __launch_bounds__(128) proj_kernel(const float* __restrict__ x,
                                                   const float* __restrict__ W) {
    __shared__ float xs[2][32][36];   // [buf][k][m], padded (16B-aligned rows)
    __shared__ float ws[2][32][64];   // [buf][k][n]
    const int bm = blockIdx.y * 32;
    const int bx = blockIdx.x;
    const int bn = bx * 64;
    const int tid = threadIdx.x;
    const int tx = tid & 15;          // n micro-tile
    const int ty = tid >> 4;          // m micro-tile (0..7)

    // load-role indices
    const int xr = tid >> 2;          // 0..31 (m row)
    const int xc = (tid & 3) * 8;     // k base: two float4
    const int wr = tid >> 2;          // 0..31 (k row)
    const int wc = (tid & 3) * 16;    // n base: four float4

    float acc[4][4] = {};

    // prologue: chunk 0 -> buf 0
    {
        float4 a0 = *(const float4*)&x[(size_t)(bm + xr) * DD + xc];
        float4 a1 = *(const float4*)&x[(size_t)(bm + xr) * DD + xc + 4];
        xs[0][xc + 0][xr] = a0.x; xs[0][xc + 1][xr] = a0.y;
        xs[0][xc + 2][xr] = a0.z; xs[0][xc + 3][xr] = a0.w;
        xs[0][xc + 4][xr] = a1.x; xs[0][xc + 5][xr] = a1.y;
        xs[0][xc + 6][xr] = a1.z; xs[0][xc + 7][xr] = a1.w;
#pragma unroll
        for (int j = 0; j < 4; j++)
            *(float4*)&ws[0][wr][wc + 4 * j] =
                *(const float4*)&W[(size_t)wr * PW + bn + wc + 4 * j];
    }
    __syncthreads();

#pragma unroll
    for (int ch = 0; ch < 8; ch++) {
        const int cur = ch & 1;
        const int nxt = cur ^ 1;
        const int k1 = (ch + 1) * 32;

        float4 a0, a1, w0, w1, w2, w3;
        if (ch < 7) {
            a0 = *(const float4*)&x[(size_t)(bm + xr) * DD + k1 + xc];
            a1 = *(const float4*)&x[(size_t)(bm + xr) * DD + k1 + xc + 4];
            w0 = *(const float4*)&W[(size_t)(k1 + wr) * PW + bn + wc];
            w1 = *(const float4*)&W[(size_t)(k1 + wr) * PW + bn + wc + 4];
            w2 = *(const float4*)&W[(size_t)(k1 + wr) * PW + bn + wc + 8];
            w3 = *(const float4*)&W[(size_t)(k1 + wr) * PW + bn + wc + 12];
        }

#pragma unroll
        for (int k = 0; k < 32; k++) {
            float4 av = *(const float4*)&xs[cur][k][ty * 4];
            float4 bv = *(const float4*)&ws[cur][k][tx * 4];
            float a_[4] = {av.x, av.y, av.z, av.w};
            float b_[4] = {bv.x, bv.y, bv.z, bv.w};
#pragma unroll
            for (int i = 0; i < 4; i++)
#pragma unroll
                for (int j = 0; j < 4; j++)
                    acc[i][j] = fmaf(a_[i], b_[j], acc[i][j]);
        }

        if (ch < 7) {
            xs[nxt][xc + 0][xr] = a0.x; xs[nxt][xc + 1][xr] = a0.y;
            xs[nxt][xc + 2][xr] = a0.z; xs[nxt][xc + 3][xr] = a0.w;
            xs[nxt][xc + 4][xr] = a1.x; xs[nxt][xc + 5][xr] = a1.y;
            xs[nxt][xc + 6][xr] = a1.z; xs[nxt][xc + 7][xr] = a1.w;
            *(float4*)&ws[nxt][wr][wc]      = w0;
            *(float4*)&ws[nxt][wr][wc + 4]  = w1;
            *(float4*)&ws[nxt][wr][wc + 8]  = w2;
            *(float4*)&ws[nxt][wr][wc + 12] = w3;
            __syncthreads();
        }
    }

    // epilogue: route by tile column class
    if (bx == 0) {
#pragma unroll
        for (int i = 0; i < 4; i++) {
            float4 v = make_float4(acc[i][0], acc[i][1], acc[i][2], acc[i][3]);
            *(float4*)&g_proj[(size_t)(bm + ty * 4 + i) * PW + tx * 4] = v;
        }
    } else if (bx <= 4) {
        int n0 = bn - 64 + tx * 4;
#pragma unroll
        for (int i = 0; i < 4; i++) {
            size_t base = (size_t)(bm + ty * 4 + i) * NN + n0;
#pragma unroll
            for (int j = 0; j < 4; j++)
                g_bg2[base + j].x = acc[i][j];
        }
    } else {
        int n0 = bn - 320 + tx * 4;
#pragma unroll
        for (int i = 0; i < 4; i++) {
            size_t base = (size_t)(bm + ty * 4 + i) * NN + n0;
#pragma unroll
            for (int j = 0; j < 4; j++)
                g_bg2[base + j].y = acc[i][j];
        }
    }
}

// ---------------------------------------------------------------------------
// Kernel 2: dt = softplus(proj[:,:64] @ W_dt + b_dt); write transposed
// {dt, dt*x} and out = x*delta. One block per row, 256 threads (one per d).
// ---------------------------------------------------------------------------
__global__ void dt_kernel(const float* __restrict__ x, const float* __restrict__ Wdt,
                          const float* __restrict__ bdt, const float* __restrict__ delta,
                          float* __restrict__ out) {
    int r = blockIdx.x;
    int t = threadIdx.x;
    __shared__ float sp[DT];
    if (t < DT) sp[t] = g_proj[r * PW + t];
    __syncthreads();
    float acc = bdt[t];
#pragma unroll
    for (int k = 0; k < DT; k++)
        acc = fmaf(sp[k], Wdt[k * DD + t], acc);
    float dt = fmaxf(acc, 0.f) + log1pf(__expf(-fabsf(acc)));
    float xv = x[r * DD + t];
    int b = r >> 9;            // r / LL
    int l = r & (LL - 1);
    g_ddxT[(size_t)(b * DD + t) * LL + l] = make_float2(dt, dt * xv);
    out[r * DD + t] = xv * delta[t];
}

// ---------------------------------------------------------------------------
// Kernel 3: sequential scan.
// Two CTAs per (b, d); each CTA's 4 warps cover 128 n (1 n per lane).
// 8-step double-buffered batches; dt/dtx loads are now CONTIGUOUS in l
// (transposed layout) -> one cache line per 8 steps instead of 8 sectors.
// Per-warp partial y's -> private smem; combine atomically into out.
// ---------------------------------------------------------------------------

#define LOAD_BATCH(BUF, LB) do {                                              \
    _Pragma("unroll")                                                         \
    for (int k_ = 0; k_ < 8; k_++) {                                          \
        bg[BUF][k_] = bgp[(size_t)((LB) + k_) * NN];                          \
        dd[BUF][k_] = ddp[(LB) + k_];                                         \
    }                                                                         \
} while (0)

// transposed reduction over 32 lanes: Y[k]=sum_lanes yl_[k]; Y[lane&7] -> VOUT
#define TREDUCE8(YL, VOUT) do {                                               \
    float s_, r0_, r1_, r2_, r3_, q0_, q1_;                                   \
    s_  = bt0 ? YL[0] : YL[1];                                                \
    r0_ = (bt0 ? YL[1] : YL[0]) + __shfl_xor_sync(fm, s_, 1);                 \
    s_  = bt0 ? YL[2] : YL[3];                                                \
    r1_ = (bt0 ? YL[3] : YL[2]) + __shfl_xor_sync(fm, s_, 1);                 \
    s_  = bt0 ? YL[4] : YL[5];                                                \
    r2_ = (bt0 ? YL[5] : YL[4]) + __shfl_xor_sync(fm, s_, 1);                 \
    s_  = bt0 ? YL[6] : YL[7];                                                \
    r3_ = (bt0 ? YL[7] : YL[6]) + __shfl_xor_sync(fm, s_, 1);                 \
    s_  = bt1 ? r0_ : r1_;                                                    \
    q0_ = (bt1 ? r1_ : r0_) + __shfl_xor_sync(fm, s_, 2);                     \
    s_  = bt1 ? r2_ : r3_;                                                    \
    q1_ = (bt1 ? r3_ : r2_) + __shfl_xor_sync(fm, s_, 2);                     \
    s_  = bt2 ? q0_ : q1_;                                                    \
    VOUT = (bt2 ? q1_ : q0_) + __shfl_xor_sync(fm, s_, 4);                    \
    VOUT += __shfl_xor_sync(fm, VOUT, 8);                                     \
    VOUT += __shfl_xor_sync(fm, VOUT, 16);                                    \
} while (0)

#define COMPUTE_BATCH(BUF, LB) do {                                           \
    float yl_[8];                                                             \
    _Pragma("unroll")                                                         \
    for (int k_ = 0; k_ < 8; k_++) {                                          \
        float dt_  = dd[BUF][k_].x;                                           \
        float dtx_ = dd[BUF][k_].y;                                           \
        float a_ = ex2_approx(dt_ * a2v);                                     \
        st = fmaf(a_, st, dtx_ * bg[BUF][k_].x);                              \
        yl_[k_] = st * bg[BUF][k_].y;                                         \
    }                                                                         \
    float v_;                                                                 \
    TREDUCE8(yl_, v_);                                                        \
    if (lane < 8) ypart[warp * LL + (LB) + lane] = v_;                        \
} while (0)

__global__ void __launch_bounds__(128) scan_kernel(float* __restrict__ out,
                                                   const float* __restrict__ alog) {
    __shared__ float ypart[4 * LL];   // [warp][l], 8 KB

    const int warp = threadIdx.x >> 5;
    const int lane = threadIdx.x & 31;
    const int half = blockIdx.x & 1;        // n-half
    const int bd = blockIdx.x >> 1;
    const int b = bd >> 8;
    const int d = bd & 255;
    const int n = half * 128 + warp * 32 + lane;

    float a2v = -__expf(alog[d * NN + n]) * 1.4426950408889634f;
    float st = 0.f;

    const float2* bgp = g_bg2 + (size_t)(b * LL) * NN + n;
    const float2* ddp = g_ddxT + (size_t)bd * LL;
    float* outp = out + (size_t)b * LL * DD + d;

    const unsigned fm = 0xffffffffu;
    const int bt0 = lane & 1;
    const int bt1 = (lane >> 1) & 1;
    const int bt2 = (lane >> 2) & 1;

    // double-buffered operand stages (constant-indexed register arrays)
    float2 bg[2][8];
    float2 dd[2][8];

    LOAD_BATCH(0, 0);

#pragma unroll 1
    for (int lb = 0; lb < LL; lb += 16) {
        LOAD_BATCH(1, lb + 8);
        COMPUTE_BATCH(0, lb);
        LOAD_BATCH(0, lb + 16);    // over-prefetch into padding at the end
        COMPUTE_BATCH(1, lb + 8);
    }

    __syncthreads();

    // combine this CTA's 4 warp-partials, atomically add into out
#pragma unroll
    for (int i = 0; i < 4; i++) {
        int l = threadIdx.x + i * 128;
        float y = ypart[l] + ypart[LL + l] + ypart[2 * LL + l] + ypart[3 * LL + l];
        atomicAdd(&outp[l * DD], y);
    }
}

// ---------------------------------------------------------------------------
extern "C" void kernel_launch(void* const* d_in, const int* in_sizes, int n_in,
                              void* d_out, int out_size) {
    const float* x      = (const float*)d_in[0];  // [2,512,256]
    const float* W_in   = (const float*)d_in[1];  // [256,576]
    const float* W_dt   = (const float*)d_in[2];  // [64,256]
    const float* b_dt   = (const float*)d_in[3];  // [256]
    const float* alog   = (const float*)d_in[4];  // [256,256]
    const float* delta  = (const float*)d_in[5];  // [256]
    float* out = (float*)d_out;                   // [2,512,256]

    dim3 pgrid(PW / 64, (BB * LL) / 32);          // (9, 32) = 288 CTAs
    proj_kernel<<<pgrid, 128>>>(x, W_in);

    dt_kernel<<<BB * LL, 256>>>(x, W_dt, b_dt, delta, out);

    scan_kernel<<<BB * DD * 2, 128>>>(out, alog);
}

// round 11
// speedup vs baseline: 1.1359x; 1.1359x over previous
#include <cuda_runtime.h>

#define BB 2
#define LL 512
#define DD 256
#define NN 256
#define DT 64
#define PW 576   // DT + 2*DD

// scratch (device globals — no allocations allowed); padded for the scan's
// over-prefetch past the end (values loaded but never used).
__device__ float  g_proj[(BB * LL + 16) * PW];   // [row, 576] : dt_raw | beta | gamma
__device__ float2 g_ddx [(BB * LL + 16) * DD];   // {dt, dt*x} per (row, d)
__device__ float2 g_bg2 [(BB * LL + 16) * NN];   // {beta_n, gamma_n} per (row, n)

__device__ __forceinline__ float ex2_approx(float x) {
    float r;
    asm("ex2.approx.ftz.f32 %0, %1;" : "=f"(r) : "f"(x));
    return r;
}

// ---------------------------------------------------------------------------
// Kernel 1: proj = x @ W_in   ([1024,256] x [256,576] -> [1024,576])
// 64x64 tiles, kc=32, double-buffered smem, 256 threads, 4x4 micro-tile.
// (R9 version — proven 18.8us.)
// ---------------------------------------------------------------------------
__global__ void __launch_bounds__(256) proj_kernel(const float* __restrict__ x,
                                                   const float* __restrict__ W) {
    __shared__ float xs[2][32][68];
    __shared__ float ws[2][32][64];
    const int bm = blockIdx.y * 64;
    const int bn = blockIdx.x * 64;
    const int tid = threadIdx.x;
    const int tx = tid & 15;
    const int ty = tid >> 4;

    const int xr = tid >> 2;
    const int xc = (tid & 3) * 8;
    const int wr = tid >> 3;
    const int wc = (tid & 7) * 8;

    float acc[4][4] = {};

    {
        float4 a0 = *(const float4*)&x[(size_t)(bm + xr) * DD + xc];
        float4 a1 = *(const float4*)&x[(size_t)(bm + xr) * DD + xc + 4];
        xs[0][xc + 0][xr] = a0.x; xs[0][xc + 1][xr] = a0.y;
        xs[0][xc + 2][xr] = a0.z; xs[0][xc + 3][xr] = a0.w;
        xs[0][xc + 4][xr] = a1.x; xs[0][xc + 5][xr] = a1.y;
        xs[0][xc + 6][xr] = a1.z; xs[0][xc + 7][xr] = a1.w;
        *(float4*)&ws[0][wr][wc]     = *(const float4*)&W[(size_t)wr * PW + bn + wc];
        *(float4*)&ws[0][wr][wc + 4] = *(const float4*)&W[(size_t)wr * PW + bn + wc + 4];
    }
    __syncthreads();

#pragma unroll
    for (int ch = 0; ch < 8; ch++) {
        const int cur = ch & 1;
        const int nxt = cur ^ 1;
        const int k1 = (ch + 1) * 32;

        float4 a0, a1, w0, w1;
        if (ch < 7) {
            a0 = *(const float4*)&x[(size_t)(bm + xr) * DD + k1 + xc];
            a1 = *(const float4*)&x[(size_t)(bm + xr) * DD + k1 + xc + 4];
            w0 = *(const float4*)&W[(size_t)(k1 + wr) * PW + bn + wc];
            w1 = *(const float4*)&W[(size_t)(k1 + wr) * PW + bn + wc + 4];
        }

#pragma unroll
        for (int k = 0; k < 32; k++) {
            float4 av = *(const float4*)&xs[cur][k][ty * 4];
            float4 bv = *(const float4*)&ws[cur][k][tx * 4];
            float a_[4] = {av.x, av.y, av.z, av.w};
            float b_[4] = {bv.x, bv.y, bv.z, bv.w};
#pragma unroll
            for (int i = 0; i < 4; i++)
#pragma unroll
                for (int j = 0; j < 4; j++)
                    acc[i][j] = fmaf(a_[i], b_[j], acc[i][j]);
        }

        if (ch < 7) {
            xs[nxt][xc + 0][xr] = a0.x; xs[nxt][xc + 1][xr] = a0.y;
            xs[nxt][xc + 2][xr] = a0.z; xs[nxt][xc + 3][xr] = a0.w;
            xs[nxt][xc + 4][xr] = a1.x; xs[nxt][xc + 5][xr] = a1.y;
            xs[nxt][xc + 6][xr] = a1.z; xs[nxt][xc + 7][xr] = a1.w;
            *(float4*)&ws[nxt][wr][wc]     = w0;
            *(float4*)&ws[nxt][wr][wc + 4] = w1;
            __syncthreads();
        }
    }

#pragma unroll
    for (int i = 0; i < 4; i++) {
        float4 v = make_float4(acc[i][0], acc[i][1], acc[i][2], acc[i][3]);
        *(float4*)&g_proj[(size_t)(bm + ty * 4 + i) * PW + bn + tx * 4] = v;
    }
}

// ---------------------------------------------------------------------------
// Kernel 2 (fused): dt = softplus(proj[:,:64] @ W_dt + b_dt); pack {dt, dt*x};
// out = x*delta; pack {beta, gamma} per n.  (R9 version — all coalesced.)
// ---------------------------------------------------------------------------
__global__ void dt_kernel(const float* __restrict__ x, const float* __restrict__ Wdt,
                          const float* __restrict__ bdt, const float* __restrict__ delta,
                          float* __restrict__ out) {
    int r = blockIdx.x;
    int t = threadIdx.x;
    __shared__ float sp[DT];
    if (t < DT) sp[t] = g_proj[r * PW + t];
    __syncthreads();
    float acc = bdt[t];
#pragma unroll
    for (int k = 0; k < DT; k++)
        acc = fmaf(sp[k], Wdt[k * DD + t], acc);
    float dt = fmaxf(acc, 0.f) + log1pf(__expf(-fabsf(acc)));
    float xv = x[r * DD + t];
    int idx = r * DD + t;
    g_ddx[idx] = make_float2(dt, dt * xv);
    out[idx]   = xv * delta[t];
    float be = g_proj[r * PW + DT + t];
    float ga = g_proj[r * PW + DT + DD + t];
    g_bg2[(size_t)r * NN + t] = make_float2(be, ga);
}

// ---------------------------------------------------------------------------
// Kernel 3: sequential scan.
// ONE CTA per (b, d) (512 CTAs, 128 threads); each lane owns 2 n.
// dd (dt/dtx) preloaded to smem once per CTA (shared by all warps, LDS in the
// hot loop). bg loads are one LDG.128 per lane per step ({b0,g0,b1,g1}).
// Per-warp partial y's -> smem; final combine does plain read-add-write.
// ---------------------------------------------------------------------------

#define LOAD_BATCH(BUF, LB) do {                                              \
    _Pragma("unroll")                                                         \
    for (int k_ = 0; k_ < 8; k_++) {                                          \
        bg[BUF][k_] = bgp[(size_t)((LB) + k_) * (NN / 2)];                    \
        dd[BUF][k_] = sdd[(LB) + k_];                                         \
    }                                                                         \
} while (0)

// transposed reduction over 32 lanes: Y[k]=sum_lanes yl_[k]; Y[lane&7] -> VOUT
#define TREDUCE8(YL, VOUT) do {                                               \
    float s_, r0_, r1_, r2_, r3_, q0_, q1_;                                   \
    s_  = bt0 ? YL[0] : YL[1];                                                \
    r0_ = (bt0 ? YL[1] : YL[0]) + __shfl_xor_sync(fm, s_, 1);                 \
    s_  = bt0 ? YL[2] : YL[3];                                                \
    r1_ = (bt0 ? YL[3] : YL[2]) + __shfl_xor_sync(fm, s_, 1);                 \
    s_  = bt0 ? YL[4] : YL[5];                                                \
    r2_ = (bt0 ? YL[5] : YL[4]) + __shfl_xor_sync(fm, s_, 1);                 \
    s_  = bt0 ? YL[6] : YL[7];                                                \
    r3_ = (bt0 ? YL[7] : YL[6]) + __shfl_xor_sync(fm, s_, 1);                 \
    s_  = bt1 ? r0_ : r1_;                                                    \
    q0_ = (bt1 ? r1_ : r0_) + __shfl_xor_sync(fm, s_, 2);                     \
    s_  = bt1 ? r2_ : r3_;                                                    \
    q1_ = (bt1 ? r3_ : r2_) + __shfl_xor_sync(fm, s_, 2);                     \
    s_  = bt2 ? q0_ : q1_;                                                    \
    VOUT = (bt2 ? q1_ : q0_) + __shfl_xor_sync(fm, s_, 4);                    \
    VOUT += __shfl_xor_sync(fm, VOUT, 8);                                     \
    VOUT += __shfl_xor_sync(fm, VOUT, 16);                                    \
} while (0)

#define COMPUTE_BATCH(BUF, LB) do {                                           \
    float yl_[8];                                                             \
    _Pragma("unroll")                                                         \
    for (int k_ = 0; k_ < 8; k_++) {                                          \
        float dt_  = dd[BUF][k_].x;                                           \
        float dtx_ = dd[BUF][k_].y;                                           \
        float a0_ = ex2_approx(dt_ * a2v0);                                   \
        float a1_ = ex2_approx(dt_ * a2v1);                                   \
        st0 = fmaf(a0_, st0, dtx_ * bg[BUF][k_].x);                           \
        st1 = fmaf(a1_, st1, dtx_ * bg[BUF][k_].z);                           \
        yl_[k_] = fmaf(st0, bg[BUF][k_].y, st1 * bg[BUF][k_].w);              \
    }                                                                         \
    float v_;                                                                 \
    TREDUCE8(yl_, v_);                                                        \
    if (lane < 8) ypart[warp * LL + (LB) + lane] = v_;                        \
} while (0)

__global__ void __launch_bounds__(128, 4) scan_kernel(float* __restrict__ out,
                                                      const float* __restrict__ alog) {
    __shared__ float2 sdd[LL + 16];   // {dt, dt*x} for all 512 steps (+pad)
    __shared__ float  ypart[4 * LL];  // [warp][l], 8 KB

    const int warp = threadIdx.x >> 5;
    const int lane = threadIdx.x & 31;
    const int bd = blockIdx.x;
    const int b = bd >> 8;
    const int d = bd & 255;
    const int p = warp * 32 + lane;   // n-pair index: n = 2p, 2p+1

    // one-time dd preload (shared by all 4 warps for the whole scan)
    for (int i = threadIdx.x; i < LL; i += 128)
        sdd[i] = g_ddx[(size_t)(b * LL + i) * DD + d];
    __syncthreads();

    const float L2E = 1.4426950408889634f;
    float a2v0 = -__expf(alog[d * NN + 2 * p])     * L2E;
    float a2v1 = -__expf(alog[d * NN + 2 * p + 1]) * L2E;
    float st0 = 0.f, st1 = 0.f;

    // bg rows as float4: element p = {be_{2p}, ga_{2p}, be_{2p+1}, ga_{2p+1}}
    const float4* bgp = (const float4*)(g_bg2 + (size_t)(b * LL) * NN) + p;
    float* outp = out + (size_t)b * LL * DD + d;

    const unsigned fm = 0xffffffffu;
    const int bt0 = lane & 1;
    const int bt1 = (lane >> 1) & 1;
    const int bt2 = (lane >> 2) & 1;

    float4 bg[2][8];
    float2 dd[2][8];

    LOAD_BATCH(0, 0);

#pragma unroll 1
    for (int lb = 0; lb < LL; lb += 16) {
        LOAD_BATCH(1, lb + 8);
        COMPUTE_BATCH(0, lb);
        LOAD_BATCH(0, lb + 16);    // over-prefetch lands in padding (unused)
        COMPUTE_BATCH(1, lb + 8);
    }

    __syncthreads();

    // final combine: single owner CTA -> plain read-add-write (no atomics)
#pragma unroll
    for (int i = 0; i < 4; i++) {
        int l = threadIdx.x + i * 128;
        float y = ypart[l] + ypart[LL + l] + ypart[2 * LL + l] + ypart[3 * LL + l];
        outp[l * DD] += y;
    }
}

// ---------------------------------------------------------------------------
extern "C" void kernel_launch(void* const* d_in, const int* in_sizes, int n_in,
                              void* d_out, int out_size) {
    const float* x      = (const float*)d_in[0];  // [2,512,256]
    const float* W_in   = (const float*)d_in[1];  // [256,576]
    const float* W_dt   = (const float*)d_in[2];  // [64,256]
    const float* b_dt   = (const float*)d_in[3];  // [256]
    const float* alog   = (const float*)d_in[4];  // [256,256]
    const float* delta  = (const float*)d_in[5];  // [256]
    float* out = (float*)d_out;                   // [2,512,256]

    dim3 pgrid(PW / 64, (BB * LL) / 64);          // (9, 16) = 144 CTAs
    proj_kernel<<<pgrid, 256>>>(x, W_in);

    dt_kernel<<<BB * LL, 256>>>(x, W_dt, b_dt, delta, out);

    scan_kernel<<<BB * DD, 128>>>(out, alog);
}

// round 12
// speedup vs baseline: 1.1619x; 1.0229x over previous
#include <cuda_runtime.h>

#define BB 2
#define LL 512
#define DD 256
#define NN 256
#define DT 64
#define PW 576   // DT + 2*DD

// scratch (device globals — no allocations allowed); padded for the scan's
// over-prefetch past the end (values loaded but never used).
__device__ float  g_proj[(BB * LL + 16) * PW];   // [row, 576] : dt_raw | beta | gamma
__device__ float2 g_ddx [(BB * LL + 16) * DD];   // {dt, dt*x} per (row, d)
__device__ float2 g_bg2 [(BB * LL + 16) * NN];   // {beta_n, gamma_n} per (row, n)

__device__ __forceinline__ float ex2_approx(float x) {
    float r;
    asm("ex2.approx.ftz.f32 %0, %1;" : "=f"(r) : "f"(x));
    return r;
}

// ---------------------------------------------------------------------------
// Kernel 1: proj = x @ W_in   ([1024,256] x [256,576] -> [1024,576])
// 64x64 tiles, kc=32, double-buffered smem, 256 threads, 4x4 micro-tile.
// NEW: register-level double-buffering of the LDS operand stream — the
// k+1 operands are loaded before k's FMAs, hiding the 29-cycle LDS latency.
// ---------------------------------------------------------------------------
__global__ void __launch_bounds__(256) proj_kernel(const float* __restrict__ x,
                                                   const float* __restrict__ W) {
    __shared__ float xs[2][32][68];
    __shared__ float ws[2][32][64];
    const int bm = blockIdx.y * 64;
    const int bn = blockIdx.x * 64;
    const int tid = threadIdx.x;
    const int tx = tid & 15;
    const int ty = tid >> 4;

    const int xr = tid >> 2;
    const int xc = (tid & 3) * 8;
    const int wr = tid >> 3;
    const int wc = (tid & 7) * 8;

    float acc[4][4] = {};

    {
        float4 a0 = *(const float4*)&x[(size_t)(bm + xr) * DD + xc];
        float4 a1 = *(const float4*)&x[(size_t)(bm + xr) * DD + xc + 4];
        xs[0][xc + 0][xr] = a0.x; xs[0][xc + 1][xr] = a0.y;
        xs[0][xc + 2][xr] = a0.z; xs[0][xc + 3][xr] = a0.w;
        xs[0][xc + 4][xr] = a1.x; xs[0][xc + 5][xr] = a1.y;
        xs[0][xc + 6][xr] = a1.z; xs[0][xc + 7][xr] = a1.w;
        *(float4*)&ws[0][wr][wc]     = *(const float4*)&W[(size_t)wr * PW + bn + wc];
        *(float4*)&ws[0][wr][wc + 4] = *(const float4*)&W[(size_t)wr * PW + bn + wc + 4];
    }
    __syncthreads();

#pragma unroll
    for (int ch = 0; ch < 8; ch++) {
        const int cur = ch & 1;
        const int nxt = cur ^ 1;
        const int k1 = (ch + 1) * 32;

        // global prefetch for next chunk
        float4 a0, a1, w0, w1;
        if (ch < 7) {
            a0 = *(const float4*)&x[(size_t)(bm + xr) * DD + k1 + xc];
            a1 = *(const float4*)&x[(size_t)(bm + xr) * DD + k1 + xc + 4];
            w0 = *(const float4*)&W[(size_t)(k1 + wr) * PW + bn + wc];
            w1 = *(const float4*)&W[(size_t)(k1 + wr) * PW + bn + wc + 4];
        }

        // register-level LDS pipeline: load k+1 before computing k
        float4 av0 = *(const float4*)&xs[cur][0][ty * 4];
        float4 bv0 = *(const float4*)&ws[cur][0][tx * 4];
#pragma unroll
        for (int k = 0; k < 32; k++) {
            float4 av1, bv1;
            if (k < 31) {
                av1 = *(const float4*)&xs[cur][k + 1][ty * 4];
                bv1 = *(const float4*)&ws[cur][k + 1][tx * 4];
            }
            float a_[4] = {av0.x, av0.y, av0.z, av0.w};
            float b_[4] = {bv0.x, bv0.y, bv0.z, bv0.w};
#pragma unroll
            for (int i = 0; i < 4; i++)
#pragma unroll
                for (int j = 0; j < 4; j++)
                    acc[i][j] = fmaf(a_[i], b_[j], acc[i][j]);
            av0 = av1; bv0 = bv1;
        }

        if (ch < 7) {
            xs[nxt][xc + 0][xr] = a0.x; xs[nxt][xc + 1][xr] = a0.y;
            xs[nxt][xc + 2][xr] = a0.z; xs[nxt][xc + 3][xr] = a0.w;
            xs[nxt][xc + 4][xr] = a1.x; xs[nxt][xc + 5][xr] = a1.y;
            xs[nxt][xc + 6][xr] = a1.z; xs[nxt][xc + 7][xr] = a1.w;
            *(float4*)&ws[nxt][wr][wc]     = w0;
            *(float4*)&ws[nxt][wr][wc + 4] = w1;
            __syncthreads();
        }
    }

#pragma unroll
    for (int i = 0; i < 4; i++) {
        float4 v = make_float4(acc[i][0], acc[i][1], acc[i][2], acc[i][3]);
        *(float4*)&g_proj[(size_t)(bm + ty * 4 + i) * PW + bn + tx * 4] = v;
    }
}

// ---------------------------------------------------------------------------
// Kernel 2 (fused): dt = softplus(proj[:,:64] @ W_dt + b_dt); pack {dt, dt*x};
// out = x*delta; pack {beta, gamma} per n.  (unchanged — all coalesced.)
// ---------------------------------------------------------------------------
__global__ void dt_kernel(const float* __restrict__ x, const float* __restrict__ Wdt,
                          const float* __restrict__ bdt, const float* __restrict__ delta,
                          float* __restrict__ out) {
    int r = blockIdx.x;
    int t = threadIdx.x;
    __shared__ float sp[DT];
    if (t < DT) sp[t] = g_proj[r * PW + t];
    __syncthreads();
    float acc = bdt[t];
#pragma unroll
    for (int k = 0; k < DT; k++)
        acc = fmaf(sp[k], Wdt[k * DD + t], acc);
    float dt = fmaxf(acc, 0.f) + log1pf(__expf(-fabsf(acc)));
    float xv = x[r * DD + t];
    int idx = r * DD + t;
    g_ddx[idx] = make_float2(dt, dt * xv);
    out[idx]   = xv * delta[t];
    float be = g_proj[r * PW + DT + t];
    float ga = g_proj[r * PW + DT + DD + t];
    g_bg2[(size_t)r * NN + t] = make_float2(be, ga);
}

// ---------------------------------------------------------------------------
// Kernel 3: sequential scan.  (unchanged from R11 — proven.)
// ONE CTA per (b, d) (512 CTAs, 128 threads); each lane owns 2 n.
// dd preloaded to smem once per CTA; bg via one LDG.128 per lane per step.
// ---------------------------------------------------------------------------

#define LOAD_BATCH(BUF, LB) do {                                              \
    _Pragma("unroll")                                                         \
    for (int k_ = 0; k_ < 8; k_++) {                                          \
        bg[BUF][k_] = bgp[(size_t)((LB) + k_) * (NN / 2)];                    \
        dd[BUF][k_] = sdd[(LB) + k_];                                         \
    }                                                                         \
} while (0)

#define TREDUCE8(YL, VOUT) do {                                               \
    float s_, r0_, r1_, r2_, r3_, q0_, q1_;                                   \
    s_  = bt0 ? YL[0] : YL[1];                                                \
    r0_ = (bt0 ? YL[1] : YL[0]) + __shfl_xor_sync(fm, s_, 1);                 \
    s_  = bt0 ? YL[2] : YL[3];                                                \
    r1_ = (bt0 ? YL[3] : YL[2]) + __shfl_xor_sync(fm, s_, 1);                 \
    s_  = bt0 ? YL[4] : YL[5];                                                \
    r2_ = (bt0 ? YL[5] : YL[4]) + __shfl_xor_sync(fm, s_, 1);                 \
    s_  = bt0 ? YL[6] : YL[7];                                                \
    r3_ = (bt0 ? YL[7] : YL[6]) + __shfl_xor_sync(fm, s_, 1);                 \
    s_  = bt1 ? r0_ : r1_;                                                    \
    q0_ = (bt1 ? r1_ : r0_) + __shfl_xor_sync(fm, s_, 2);                     \
    s_  = bt1 ? r2_ : r3_;                                                    \
    q1_ = (bt1 ? r3_ : r2_) + __shfl_xor_sync(fm, s_, 2);                     \
    s_  = bt2 ? q0_ : q1_;                                                    \
    VOUT = (bt2 ? q1_ : q0_) + __shfl_xor_sync(fm, s_, 4);                    \
    VOUT += __shfl_xor_sync(fm, VOUT, 8);                                     \
    VOUT += __shfl_xor_sync(fm, VOUT, 16);                                    \
} while (0)

#define COMPUTE_BATCH(BUF, LB) do {                                           \
    float yl_[8];                                                             \
    _Pragma("unroll")                                                         \
    for (int k_ = 0; k_ < 8; k_++) {                                          \
        float dt_  = dd[BUF][k_].x;                                           \
        float dtx_ = dd[BUF][k_].y;                                           \
        float a0_ = ex2_approx(dt_ * a2v0);                                   \
        float a1_ = ex2_approx(dt_ * a2v1);                                   \
        st0 = fmaf(a0_, st0, dtx_ * bg[BUF][k_].x);                           \
        st1 = fmaf(a1_, st1, dtx_ * bg[BUF][k_].z);                           \
        yl_[k_] = fmaf(st0, bg[BUF][k_].y, st1 * bg[BUF][k_].w);              \
    }                                                                         \
    float v_;                                                                 \
    TREDUCE8(yl_, v_);                                                        \
    if (lane < 8) ypart[warp * LL + (LB) + lane] = v_;                        \
} while (0)

__global__ void __launch_bounds__(128, 4) scan_kernel(float* __restrict__ out,
                                                      const float* __restrict__ alog) {
    __shared__ float2 sdd[LL + 16];
    __shared__ float  ypart[4 * LL];

    const int warp = threadIdx.x >> 5;
    const int lane = threadIdx.x & 31;
    const int bd = blockIdx.x;
    const int b = bd >> 8;
    const int d = bd & 255;
    const int p = warp * 32 + lane;   // n-pair index: n = 2p, 2p+1

    for (int i = threadIdx.x; i < LL; i += 128)
        sdd[i] = g_ddx[(size_t)(b * LL + i) * DD + d];
    __syncthreads();

    const float L2E = 1.4426950408889634f;
    float a2v0 = -__expf(alog[d * NN + 2 * p])     * L2E;
    float a2v1 = -__expf(alog[d * NN + 2 * p + 1]) * L2E;
    float st0 = 0.f, st1 = 0.f;

    const float4* bgp = (const float4*)(g_bg2 + (size_t)(b * LL) * NN) + p;
    float* outp = out + (size_t)b * LL * DD + d;

    const unsigned fm = 0xffffffffu;
    const int bt0 = lane & 1;
    const int bt1 = (lane >> 1) & 1;
    const int bt2 = (lane >> 2) & 1;

    float4 bg[2][8];
    float2 dd[2][8];

    LOAD_BATCH(0, 0);

#pragma unroll 1
    for (int lb = 0; lb < LL; lb += 16) {
        LOAD_BATCH(1, lb + 8);
        COMPUTE_BATCH(0, lb);
        LOAD_BATCH(0, lb + 16);    // over-prefetch lands in padding (unused)
        COMPUTE_BATCH(1, lb + 8);
    }

    __syncthreads();

#pragma unroll
    for (int i = 0; i < 4; i++) {
        int l = threadIdx.x + i * 128;
        float y = ypart[l] + ypart[LL + l] + ypart[2 * LL + l] + ypart[3 * LL + l];
        outp[l * DD] += y;
    }
}

// ---------------------------------------------------------------------------
extern "C" void kernel_launch(void* const* d_in, const int* in_sizes, int n_in,
                              void* d_out, int out_size) {
    const float* x      = (const float*)d_in[0];  // [2,512,256]
    const float* W_in   = (const float*)d_in[1];  // [256,576]
    const float* W_dt   = (const float*)d_in[2];  // [64,256]
    const float* b_dt   = (const float*)d_in[3];  // [256]
    const float* alog   = (const float*)d_in[4];  // [256,256]
    const float* delta  = (const float*)d_in[5];  // [256]
    float* out = (float*)d_out;                   // [2,512,256]

    dim3 pgrid(PW / 64, (BB * LL) / 64);          // (9, 16) = 144 CTAs
    proj_kernel<<<pgrid, 256>>>(x, W_in);

    dt_kernel<<<BB * LL, 256>>>(x, W_dt, b_dt, delta, out);

    scan_kernel<<<BB * DD, 128>>>(out, alog);
}